// round 1
// baseline (speedup 1.0000x reference)
#include <cuda_runtime.h>
#include <math.h>

#define NB   8
#define NH   16
#define LQ   128
#define LC   4096
#define DD   1024
#define HL   (NH * LQ)   // 2048
#define TOPK 5
#define EPS  1e-8f
#define NEG_HUGE (-3.4e38f)

// Scratch (allocation-free rule: __device__ globals)
__device__ float g_avg[NB * LC];    // sums of attn over (h, lq)
__device__ float g_qvec[NB * DD];   // sums of question over lq
__device__ float g_bloss[NB];       // per-batch loss

// ---------------------------------------------------------------------------
// 0. Zero scratch (graph replays require re-zeroing every launch)
// ---------------------------------------------------------------------------
__global__ void zero_kernel() {
    int i = blockIdx.x * blockDim.x + threadIdx.x;
    if (i < NB * LC) g_avg[i] = 0.0f;
    if (i < NB * DD) g_qvec[i] = 0.0f;
    if (i < NB)      g_bloss[i] = 0.0f;
}

// ---------------------------------------------------------------------------
// 1. Sum cross_attn_weights over (h, lq)  ->  g_avg[b, lc]   (256 MB read)
// grid: (LC/1024, 32 segments, NB), block: 256 threads, float4 per thread
// ---------------------------------------------------------------------------
__global__ void attn_reduce(const float4* __restrict__ w) {
    const int cchunk = blockIdx.x;           // 0..3   (chunk of 1024 lc)
    const int seg    = blockIdx.y;           // 0..31  (segment of 64 rows)
    const int b      = blockIdx.z;           // 0..7
    const int lc4    = cchunk * 256 + threadIdx.x;   // float4 col, 0..1023
    const int ROWS   = HL / 32;              // 64

    float4 acc = make_float4(0.f, 0.f, 0.f, 0.f);
    size_t base = ((size_t)b * HL + (size_t)seg * ROWS) * (LC / 4) + lc4;

    #pragma unroll 8
    for (int r = 0; r < ROWS; r++) {
        float4 v = w[base + (size_t)r * (LC / 4)];
        acc.x += v.x; acc.y += v.y; acc.z += v.z; acc.w += v.w;
    }

    float* dst = &g_avg[b * LC + lc4 * 4];
    atomicAdd(dst + 0, acc.x);
    atomicAdd(dst + 1, acc.y);
    atomicAdd(dst + 2, acc.z);
    atomicAdd(dst + 3, acc.w);
}

// ---------------------------------------------------------------------------
// 2. Sum question_emb over lq -> g_qvec[b, d]   (4 MB read)
// grid: (8 lq-segments, NB), block: 256 threads (256 * float4 = D)
// ---------------------------------------------------------------------------
__global__ void qvec_reduce(const float4* __restrict__ q) {
    const int seg = blockIdx.x;   // 0..7, 16 lq rows each
    const int b   = blockIdx.y;
    const int tid = threadIdx.x;  // float4 index over D

    float4 acc = make_float4(0.f, 0.f, 0.f, 0.f);
    size_t base = ((size_t)b * LQ + (size_t)seg * 16) * (DD / 4) + tid;

    #pragma unroll
    for (int r = 0; r < 16; r++) {
        float4 v = q[base + (size_t)r * (DD / 4)];
        acc.x += v.x; acc.y += v.y; acc.z += v.z; acc.w += v.w;
    }

    float* dst = &g_qvec[b * DD + tid * 4];
    atomicAdd(dst + 0, acc.x);
    atomicAdd(dst + 1, acc.y);
    atomicAdd(dst + 2, acc.z);
    atomicAdd(dst + 3, acc.w);
}

// ---------------------------------------------------------------------------
// 3. Per-batch: top-5 argmax (min-index tie-break, matching jax top_k),
//    gather 5 context rows, cosine sim vs mean question vector.
// grid: NB blocks, block: 256 threads
// ---------------------------------------------------------------------------
__global__ void topk_kernel(const float* __restrict__ ctx) {
    __shared__ float  s_attn[LC];       // 16 KB
    __shared__ float4 s_q[DD / 4];      // 4 KB
    __shared__ float2 s_red[256];
    __shared__ int    s_ridx[256];
    __shared__ int    s_top[TOPK];
    __shared__ float  s_qnorm;

    const int b   = blockIdx.x;
    const int tid = threadIdx.x;

    // mean question vector for this batch
    float4 q4 = reinterpret_cast<const float4*>(g_qvec)[b * (DD / 4) + tid];
    const float inv = 1.0f / (float)LQ;
    q4.x *= inv; q4.y *= inv; q4.z *= inv; q4.w *= inv;
    s_q[tid] = q4;
    s_red[tid].x = q4.x * q4.x + q4.y * q4.y + q4.z * q4.z + q4.w * q4.w;
    __syncthreads();
    for (int s = 128; s > 0; s >>= 1) {
        if (tid < s) s_red[tid].x += s_red[tid + s].x;
        __syncthreads();
    }
    if (tid == 0) s_qnorm = fmaxf(sqrtf(s_red[0].x), EPS);

    // stage avg_attn (sums; constant scale doesn't affect ordering)
    for (int i = tid; i < LC; i += 256) s_attn[i] = g_avg[b * LC + i];
    __syncthreads();

    // 5 rounds of argmax with min-index tie-break
    for (int k = 0; k < TOPK; k++) {
        float bv = NEG_HUGE; int bi = 0;
        for (int i = tid; i < LC; i += 256) {
            float v = s_attn[i];
            if (v > bv) { bv = v; bi = i; }   // strict > keeps smallest i per thread
        }
        s_red[tid].x = bv; s_ridx[tid] = bi;
        __syncthreads();
        for (int s = 128; s > 0; s >>= 1) {
            if (tid < s) {
                float v2 = s_red[tid + s].x; int i2 = s_ridx[tid + s];
                if (v2 > s_red[tid].x ||
                    (v2 == s_red[tid].x && i2 < s_ridx[tid])) {
                    s_red[tid].x = v2; s_ridx[tid] = i2;
                }
            }
            __syncthreads();
        }
        if (tid == 0) { s_top[k] = s_ridx[0]; s_attn[s_ridx[0]] = NEG_HUGE; }
        __syncthreads();
    }

    // cosine similarity against the 5 gathered context rows (only 20 KB read!)
    float loss = 0.0f;
    for (int k = 0; k < TOPK; k++) {
        const float4* c = reinterpret_cast<const float4*>(
            ctx + ((size_t)b * LC + (size_t)s_top[k]) * DD);
        float4 cv = c[tid];
        float4 qq = s_q[tid];
        float d  = cv.x * qq.x + cv.y * qq.y + cv.z * qq.z + cv.w * qq.w;
        float cs = cv.x * cv.x + cv.y * cv.y + cv.z * cv.z + cv.w * cv.w;
        s_red[tid] = make_float2(d, cs);
        __syncthreads();
        for (int s = 128; s > 0; s >>= 1) {
            if (tid < s) {
                s_red[tid].x += s_red[tid + s].x;
                s_red[tid].y += s_red[tid + s].y;
            }
            __syncthreads();
        }
        if (tid == 0) {
            float cn  = fmaxf(sqrtf(s_red[0].y), EPS);
            float sim = s_red[0].x / (s_qnorm * cn);
            loss += 1.0f - sim;
        }
        __syncthreads();
    }
    if (tid == 0) g_bloss[b] = loss;
}

// ---------------------------------------------------------------------------
// 4. Final scalar: mean over B*TOPK
// ---------------------------------------------------------------------------
__global__ void final_kernel(float* __restrict__ out) {
    if (threadIdx.x == 0) {
        float s = 0.0f;
        for (int b = 0; b < NB; b++) s += g_bloss[b];
        out[0] = s / (float)(NB * TOPK);
    }
}

// ---------------------------------------------------------------------------
extern "C" void kernel_launch(void* const* d_in, const int* in_sizes, int n_in,
                              void* d_out, int out_size) {
    const float* q   = (const float*)d_in[0];  // question_emb  [8,128,1024]
    const float* ctx = (const float*)d_in[1];  // context_emb   [8,4096,1024]
    const float* w   = (const float*)d_in[2];  // cross_attn    [8,16,128,4096]

    zero_kernel<<<(NB * LC + 255) / 256, 256>>>();

    dim3 g1(LC / 1024, 32, NB);   // 4 x 32 x 8 = 1024 blocks
    attn_reduce<<<g1, 256>>>((const float4*)w);

    dim3 g2(8, NB);               // 64 blocks
    qvec_reduce<<<g2, 256>>>((const float4*)q);

    topk_kernel<<<NB, 256>>>(ctx);

    final_kernel<<<1, 32>>>((float*)d_out);
}

// round 2
// speedup vs baseline: 1.1523x; 1.1523x over previous
#include <cuda_runtime.h>
#include <math.h>

#define NB   8
#define NH   16
#define LQ   128
#define LC   4096
#define DD   1024
#define HL   (NH * LQ)   // 2048
#define TOPK 5
#define EPS  1e-8f
#define NEG_HUGE (-3.4e38f)

// Scratch (allocation-free rule: __device__ globals)
__device__ float g_avg[NB * LC];    // sums of attn over (h, lq)
__device__ float g_qvec[NB * DD];   // sums of question over lq
__device__ float g_loss_sum;
__device__ int   g_done;

// ---------------------------------------------------------------------------
// 0. Zero scratch (graph replays require re-zeroing every launch)
// ---------------------------------------------------------------------------
__global__ void zero_kernel() {
    int i = blockIdx.x * blockDim.x + threadIdx.x;
    if (i < NB * LC) g_avg[i] = 0.0f;
    if (i < NB * DD) g_qvec[i] = 0.0f;
    if (i == 0) { g_loss_sum = 0.0f; g_done = 0; }
}

// ---------------------------------------------------------------------------
// 1. Sum cross_attn_weights over (h, lq)  ->  g_avg[b, lc]   (256 MB read)
// grid: (4, 32, 8) = 1024 blocks, 256 thr, float4 coalesced along Lc
// ---------------------------------------------------------------------------
__global__ void attn_reduce(const float4* __restrict__ w) {
    const int cchunk = blockIdx.x;           // 0..3
    const int seg    = blockIdx.y;           // 0..31
    const int b      = blockIdx.z;           // 0..7
    const int lc4    = cchunk * 256 + threadIdx.x;
    const int ROWS   = HL / 32;              // 64

    float4 acc = make_float4(0.f, 0.f, 0.f, 0.f);
    size_t base = ((size_t)b * HL + (size_t)seg * ROWS) * (LC / 4) + lc4;

    #pragma unroll 16
    for (int r = 0; r < ROWS; r++) {
        float4 v = w[base + (size_t)r * (LC / 4)];
        acc.x += v.x; acc.y += v.y; acc.z += v.z; acc.w += v.w;
    }

    float* dst = &g_avg[b * LC + lc4 * 4];
    atomicAdd(dst + 0, acc.x);
    atomicAdd(dst + 1, acc.y);
    atomicAdd(dst + 2, acc.z);
    atomicAdd(dst + 3, acc.w);
}

// ---------------------------------------------------------------------------
// 2. Sum question_emb over lq -> g_qvec[b, d]   (4 MB read)
// ---------------------------------------------------------------------------
__global__ void qvec_reduce(const float4* __restrict__ q) {
    const int seg = blockIdx.x;   // 0..7 (16 lq rows each)
    const int b   = blockIdx.y;
    const int tid = threadIdx.x;

    float4 acc = make_float4(0.f, 0.f, 0.f, 0.f);
    size_t base = ((size_t)b * LQ + (size_t)seg * 16) * (DD / 4) + tid;

    #pragma unroll
    for (int r = 0; r < 16; r++) {
        float4 v = q[base + (size_t)r * (DD / 4)];
        acc.x += v.x; acc.y += v.y; acc.z += v.z; acc.w += v.w;
    }

    float* dst = &g_qvec[b * DD + tid * 4];
    atomicAdd(dst + 0, acc.x);
    atomicAdd(dst + 1, acc.y);
    atomicAdd(dst + 2, acc.z);
    atomicAdd(dst + 3, acc.w);
}

// ---------------------------------------------------------------------------
// helpers: warp reductions
// ---------------------------------------------------------------------------
__device__ __forceinline__ void warp_argmax(float& v, int& i) {
    #pragma unroll
    for (int off = 16; off > 0; off >>= 1) {
        float v2 = __shfl_down_sync(0xffffffffu, v, off);
        int   i2 = __shfl_down_sync(0xffffffffu, i, off);
        if (v2 > v || (v2 == v && i2 < i)) { v = v2; i = i2; }
    }
}
__device__ __forceinline__ float warp_sum(float v) {
    #pragma unroll
    for (int off = 16; off > 0; off >>= 1)
        v += __shfl_down_sync(0xffffffffu, v, off);
    return v;
}

// ---------------------------------------------------------------------------
// 3. Fused tail: per-batch top-5 (min-index tie-break, matches jax top_k),
//    mean-q cosine vs gathered rows, and global mean written by last block.
// grid: NB blocks x 1024 threads (32 warps)
// ---------------------------------------------------------------------------
__global__ void __launch_bounds__(1024, 1)
tail_kernel(const float* __restrict__ ctx, float* __restrict__ out) {
    __shared__ float s_attn[LC];        // 16 KB
    __shared__ float s_q[DD];           // 4 KB
    __shared__ float s_wv[32];
    __shared__ int   s_wi[32];
    __shared__ float s_wd[32], s_wc[32];
    __shared__ int   s_top[TOPK];
    __shared__ float s_qnorm;

    const int b    = blockIdx.x;
    const int tid  = threadIdx.x;
    const int lane = tid & 31;
    const int wid  = tid >> 5;

    // --- mean question vector + its norm -------------------------------
    float qm = g_qvec[b * DD + tid] * (1.0f / (float)LQ);
    s_q[tid] = qm;
    {
        float ps = warp_sum(qm * qm);
        if (lane == 0) s_wv[wid] = ps;
    }

    // --- stage avg_attn (sums; scale-invariant ordering) ----------------
    #pragma unroll
    for (int j = 0; j < 4; j++)
        s_attn[tid + j * 1024] = g_avg[b * LC + tid + j * 1024];
    __syncthreads();

    if (wid == 0) {
        float v = s_wv[lane];
        v = warp_sum(v);
        if (lane == 0) s_qnorm = fmaxf(sqrtf(v), EPS);
    }

    // --- 5 rounds of argmax with min-index tie-break ---------------------
    for (int k = 0; k < TOPK; k++) {
        float bv = NEG_HUGE; int bi = 0;
        #pragma unroll
        for (int j = 0; j < 4; j++) {
            int i = tid + j * 1024;           // ascending i per thread
            float v = s_attn[i];
            if (v > bv) { bv = v; bi = i; }   // strict > keeps smallest i
        }
        warp_argmax(bv, bi);
        if (lane == 0) { s_wv[wid] = bv; s_wi[wid] = bi; }
        __syncthreads();
        if (wid == 0) {
            float v = s_wv[lane]; int i = s_wi[lane];
            warp_argmax(v, i);
            if (lane == 0) { s_top[k] = i; s_attn[i] = NEG_HUGE; }
        }
        __syncthreads();
    }

    // --- prefetch all 5 context rows in parallel (one DRAM round-trip) ---
    float cv[TOPK];
    #pragma unroll
    for (int k = 0; k < TOPK; k++)
        cv[k] = ctx[((size_t)b * LC + (size_t)s_top[k]) * DD + tid];

    // --- cosine similarities ---------------------------------------------
    const float qv = s_q[tid];
    float loss = 0.0f;
    #pragma unroll
    for (int k = 0; k < TOPK; k++) {
        float d  = warp_sum(cv[k] * qv);
        float cn = warp_sum(cv[k] * cv[k]);
        if (lane == 0) { s_wd[wid] = d; s_wc[wid] = cn; }
        __syncthreads();
        if (wid == 0) {
            float dd = warp_sum(s_wd[lane]);
            float cc = warp_sum(s_wc[lane]);
            if (lane == 0) {
                float cnorm = fmaxf(sqrtf(cc), EPS);
                loss += 1.0f - dd / (s_qnorm * cnorm);
            }
        }
        __syncthreads();
    }

    // --- fold into global mean; last block writes out ---------------------
    if (tid == 0) {
        atomicAdd(&g_loss_sum, loss);
        __threadfence();
        int t = atomicAdd(&g_done, 1);
        if (t == NB - 1)
            out[0] = g_loss_sum / (float)(NB * TOPK);
    }
}

// ---------------------------------------------------------------------------
extern "C" void kernel_launch(void* const* d_in, const int* in_sizes, int n_in,
                              void* d_out, int out_size) {
    const float* q   = (const float*)d_in[0];  // question_emb  [8,128,1024]
    const float* ctx = (const float*)d_in[1];  // context_emb   [8,4096,1024]
    const float* w   = (const float*)d_in[2];  // cross_attn    [8,16,128,4096]

    zero_kernel<<<(NB * LC + 255) / 256, 256>>>();

    dim3 g1(LC / 1024, 32, NB);   // 1024 blocks
    attn_reduce<<<g1, 256>>>((const float4*)w);

    dim3 g2(8, NB);               // 64 blocks
    qvec_reduce<<<g2, 256>>>((const float4*)q);

    tail_kernel<<<NB, 1024>>>(ctx, (float*)d_out);
}